// round 9
// baseline (speedup 1.0000x reference)
#include <cuda_runtime.h>
#include <cuda_bf16.h>
#include <cstdint>
#include <math.h>

// Problem constants
#define T_STEPS 1024
#define BATCH   16
#define HID     512
#define NBLK_R  64     // recurrence blocks
#define RED_P   20     // padded row stride (floats): 80 B = 16B-aligned for float4 stores

typedef unsigned long long ull;

// ------------------------- static device scratch -------------------------
__device__ float g_gx[(size_t)BATCH * T_STEPS * 4 * HID];   // gate preactivations (input part)
__device__ float g_seq[(size_t)BATCH * T_STEPS * HID];      // layer-0 output sequence
__device__ float g_hT[2][HID / 2][32];                      // double-buffered h: [par][n>>1][b*2+(n&1)]
__device__ unsigned g_flag[2][NBLK_R * 32];                 // [layer][block*32], 128B stride

// ------------------------- helpers -------------------------
__device__ __forceinline__ ull ffma2(ull a, ull b, ull c) {
    ull d;
    asm("fma.rn.f32x2 %0, %1, %2, %3;" : "=l"(d) : "l"(a), "l"(b), "l"(c));
    return d;
}
__device__ __forceinline__ ull splat2(float a) {
    ull d;
    asm("mov.b64 %0, {%1, %1};" : "=l"(d) : "f"(a));
    return d;
}
__device__ __forceinline__ float2 unpack2(ull v) {
    float2 f;
    asm("mov.b64 {%0, %1}, %2;" : "=f"(f.x), "=f"(f.y) : "l"(v));
    return f;
}
__device__ __forceinline__ float sigm(float x) { return 1.0f / (1.0f + __expf(-x)); }
__device__ __forceinline__ void st_release_gpu(unsigned* p, unsigned v) {
    asm volatile("st.release.gpu.global.u32 [%0], %1;" :: "l"(p), "r"(v) : "memory");
}
__device__ __forceinline__ unsigned ld_acquire_gpu(const unsigned* p) {
    unsigned v;
    asm volatile("ld.acquire.gpu.global.u32 %0, [%1];" : "=r"(v) : "l"(p) : "memory");
    return v;
}

// ------------------------- big GEMM: gx = A @ W^T + bias -------------------------
// A: [M=16384][K=512] row-major, W: [N=2048][K=512] row-major, C = g_gx [M][N]
// 128x128 tile, 8x8 per thread, f32x2-packed along M (row pairs).
__global__ __launch_bounds__(256) void gemm_gates(const float* __restrict__ Aext, int useSeq,
                                                  const float* __restrict__ W,
                                                  const float* __restrict__ bias) {
    const float* A = useSeq ? g_seq : Aext;
    __shared__ float As[16][128];
    __shared__ float Bs[16][128];
    const int tid = threadIdx.x;
    const int tx = tid & 15, ty = tid >> 4;
    const int bn = blockIdx.x, bm = blockIdx.y;
    const float* Ab = A + (size_t)bm * 128 * 512;
    const float* Wb = W + (size_t)bn * 128 * 512;
    const int lr = tid >> 2;
    const int lc = (tid & 3) << 2;

    ull acc2[4][8];
#pragma unroll
    for (int i = 0; i < 4; i++)
#pragma unroll
        for (int j = 0; j < 8; j++) acc2[i][j] = 0ull;

    for (int k0 = 0; k0 < 512; k0 += 16) {
        float4 a0 = *(const float4*)(Ab + (size_t)lr * 512 + k0 + lc);
        float4 a1 = *(const float4*)(Ab + (size_t)(lr + 64) * 512 + k0 + lc);
        float4 w0 = *(const float4*)(Wb + (size_t)lr * 512 + k0 + lc);
        float4 w1 = *(const float4*)(Wb + (size_t)(lr + 64) * 512 + k0 + lc);
        __syncthreads();
        As[lc + 0][lr] = a0.x; As[lc + 1][lr] = a0.y; As[lc + 2][lr] = a0.z; As[lc + 3][lr] = a0.w;
        As[lc + 0][lr + 64] = a1.x; As[lc + 1][lr + 64] = a1.y; As[lc + 2][lr + 64] = a1.z; As[lc + 3][lr + 64] = a1.w;
        Bs[lc + 0][lr] = w0.x; Bs[lc + 1][lr] = w0.y; Bs[lc + 2][lr] = w0.z; Bs[lc + 3][lr] = w0.w;
        Bs[lc + 0][lr + 64] = w1.x; Bs[lc + 1][lr + 64] = w1.y; Bs[lc + 2][lr + 64] = w1.z; Bs[lc + 3][lr + 64] = w1.w;
        __syncthreads();
#pragma unroll
        for (int k = 0; k < 16; k++) {
            ulonglong2 av0 = *(const ulonglong2*)&As[k][ty * 8];
            ulonglong2 av1 = *(const ulonglong2*)&As[k][ty * 8 + 4];
            float4 bv0 = *(const float4*)&Bs[k][tx * 8];
            float4 bv1 = *(const float4*)&Bs[k][tx * 8 + 4];
            ull ap[4] = {av0.x, av0.y, av1.x, av1.y};
            ull bp[8] = {splat2(bv0.x), splat2(bv0.y), splat2(bv0.z), splat2(bv0.w),
                         splat2(bv1.x), splat2(bv1.y), splat2(bv1.z), splat2(bv1.w)};
#pragma unroll
            for (int i = 0; i < 4; i++)
#pragma unroll
                for (int j = 0; j < 8; j++) acc2[i][j] = ffma2(ap[i], bp[j], acc2[i][j]);
        }
    }

    const int ncol = bn * 128 + tx * 8;
    float bb[8];
#pragma unroll
    for (int j = 0; j < 8; j++) bb[j] = bias[ncol + j];
    float* Cb = g_gx + (size_t)(bm * 128 + ty * 8) * 2048 + ncol;
#pragma unroll
    for (int i2 = 0; i2 < 4; i2++) {
        float r0[8], r1[8];
#pragma unroll
        for (int j = 0; j < 8; j++) {
            float2 v = unpack2(acc2[i2][j]);
            r0[j] = v.x + bb[j];
            r1[j] = v.y + bb[j];
        }
        float* p0 = Cb + (size_t)(2 * i2) * 2048;
        float* p1 = p0 + 2048;
        *(float4*)(p0)     = make_float4(r0[0], r0[1], r0[2], r0[3]);
        *(float4*)(p0 + 4) = make_float4(r0[4], r0[5], r0[6], r0[7]);
        *(float4*)(p1)     = make_float4(r1[0], r1[1], r1[2], r1[3]);
        *(float4*)(p1 + 4) = make_float4(r1[4], r1[5], r1[6], r1[7]);
    }
}

// ------------------------- persistent recurrence -------------------------
// 64 blocks x 256 threads. Block bi owns hidden units n0 = 8*bi .. +7 (32 gate rows).
// Warp w = K-slice [w*64, w*64+64); lane = gate row (0..31). Inner-loop h LDS are
// full-warp broadcasts; w_hh slice lives in registers (32 ull/thread).
// Barrier: 1 flag/block, warp-0 polling (2 flags/lane) with nanosleep backoff.
__global__ __launch_bounds__(256, 1) void lstm_rec(const float* __restrict__ w_hh,
                                                   const float* __restrict__ b_hh,
                                                   const float* __restrict__ h0,
                                                   const float* __restrict__ c0,
                                                   float* __restrict__ hfin,
                                                   int storeSeq, int layer) {
    extern __shared__ float smemf[];
    float* hs   = smemf;                     // 8192 floats (32 KB): [k2][b*2+(k&1)]
    float* red  = smemf + 8192;              // 8*32*RED_P = 5120 floats
    float* gbuf = smemf + 8192 + 5120;       // 32*16 = 512 floats
    float* bsm  = smemf + 8192 + 5120 + 512; // 32 floats

    const int tid = threadIdx.x;
    const int lane = tid & 31;
    const int wrp = tid >> 5;
    const int bi = blockIdx.x;
    const int n0 = bi * 8;
    const int r = lane;      // gate row 0..31 (gi = r>>3, ui = r&7)
    const int s = wrp;       // K-slice 0..7

    // reset the OTHER layer's flag (stream-ordered safe across launches/replays)
    if (tid == 0) g_flag[layer ^ 1][bi * 32] = 0u;

    // preload this thread's w_hh row-slice into registers (32 ull = 64 floats)
    const int grow = (r >> 3) * HID + n0 + (r & 7);
    ull wreg[32];
    {
        const float4* wrow = (const float4*)(w_hh + (size_t)grow * HID + s * 64);
#pragma unroll
        for (int i = 0; i < 16; i++) {
            float4 v = __ldg(wrow + i);
            ulonglong2 uu = *(ulonglong2*)&v;
            wreg[2 * i] = uu.x;
            wreg[2 * i + 1] = uu.y;
        }
    }
    if (tid < 32) bsm[tid] = __ldg(&b_hh[(tid >> 3) * HID + n0 + (tid & 7)]);

    float c = 0.f;
    if (tid < 128) { int u = tid >> 4, b = tid & 15; c = __ldg(&c0[b * HID + n0 + u]); }

    // combine-stage indices: thread handles rows r_a and r_a+16 for batch b0
    const int r_a = tid >> 4;        // 0..15
    const int b0 = tid & 15;
    const int r_b = r_a + 16;        // 16..31
    const int grow_a = (r_a >> 3) * HID + n0 + (r_a & 7);
    const int grow_b = (r_b >> 3) * HID + n0 + (r_b & 7);

    __syncthreads();

    for (int t = 0; t < T_STEPS; t++) {
        // prefetch gx for this step (hides DRAM latency under the barrier wait)
        float gx0 = __ldg(&g_gx[((size_t)b0 * T_STEPS + t) * 2048 + grow_a]);
        float gx1 = __ldg(&g_gx[((size_t)b0 * T_STEPS + t) * 2048 + grow_b]);

        const int par = t & 1;
        if (t == 0) {
            // stage initial h from h0 (layout transpose)
            for (int i = tid; i < 8192; i += 256) {
                int k2 = i >> 5, j = i & 31;
                hs[i] = h0[(j >> 1) * HID + 2 * k2 + (j & 1)];
            }
        } else {
            // barrier: warp 0 polls 2 flags/lane with backoff; others park at BAR
            if (wrp == 0) {
                const unsigned tgt = (unsigned)t;
                const unsigned* f0 = &g_flag[layer][lane * 32];
                const unsigned* f1 = &g_flag[layer][(lane + 32) * 32];
                bool ok = (ld_acquire_gpu(f0) >= tgt) & (ld_acquire_gpu(f1) >= tgt);
                while (!__all_sync(0xffffffffu, ok)) {
                    asm volatile("nanosleep.u32 200;");
                    if (!ok)
                        ok = (ld_acquire_gpu(f0) >= tgt) & (ld_acquire_gpu(f1) >= tgt);
                }
            }
            __syncthreads();
            // stage h (L1 bypass: written by other SMs)
            const float4* hsrc = (const float4*)&g_hT[par][0][0];
            float4* hdst = (float4*)hs;
#pragma unroll
            for (int it = 0; it < 8; it++) {
                int idx = tid + it * 256;
                hdst[idx] = __ldcg(hsrc + idx);
            }
        }
        __syncthreads();

        // GEMV slice: row r, 16 batches, K in [s*64, s*64+64), f32x2 along K.
        // h loads are warp-uniform (broadcast): lane varies only the w register.
        ull acc[16];
#pragma unroll
        for (int b = 0; b < 16; b++) acc[b] = 0ull;

        const ulonglong2* hbase = (const ulonglong2*)(hs + (s * 32) * 32);
#pragma unroll
        for (int kk = 0; kk < 32; kk++) {
            const ulonglong2* hp = hbase + kk * 8;
#pragma unroll
            for (int q = 0; q < 8; q++) {
                ulonglong2 hv = hp[q];
                acc[2 * q]     = ffma2(wreg[kk], hv.x, acc[2 * q]);
                acc[2 * q + 1] = ffma2(wreg[kk], hv.y, acc[2 * q + 1]);
            }
        }

        // pair-sum, then store this warp's partial row (no shfl: lane == row)
        float p[16];
#pragma unroll
        for (int b = 0; b < 16; b++) {
            float2 v = unpack2(acc[b]);
            p[b] = v.x + v.y;
        }
        {
            float* rp = &red[(s * 32 + r) * RED_P];   // 80B stride -> 16B-aligned
#pragma unroll
            for (int q = 0; q < 4; q++)
                *(float4*)&rp[q * 4] = make_float4(p[4 * q], p[4 * q + 1], p[4 * q + 2], p[4 * q + 3]);
        }
        __syncthreads();

        // combine 8 slice-partials + gx + bias, apply activations (2 rows/thread)
        {
            float s0 = gx0 + bsm[r_a];
            float s1 = gx1 + bsm[r_b];
#pragma unroll
            for (int si = 0; si < 8; si++) {
                s0 += red[(si * 32 + r_a) * RED_P + b0];
                s1 += red[(si * 32 + r_b) * RED_P + b0];
            }
            float a0 = sigm(s0);                           // rows 0..15: i, f
            float a1 = (r_b < 24) ? tanhf(s1) : sigm(s1);  // rows 16..23: g, 24..31: o
            gbuf[r_a * 16 + b0] = a0;
            gbuf[r_b * 16 + b0] = a1;
        }
        __syncthreads();

        if (tid < 128) {
            int u = tid >> 4, b = tid & 15;
            float iv = gbuf[(0 + u) * 16 + b];
            float fv = gbuf[(8 + u) * 16 + b];
            float gv = gbuf[(16 + u) * 16 + b];
            float ov = gbuf[(24 + u) * 16 + b];
            c = fv * c + iv * gv;
            float h = ov * tanhf(c);
            int n = n0 + u;
            g_hT[par ^ 1][n >> 1][b * 2 + (n & 1)] = h;
            if (storeSeq) g_seq[((size_t)b * T_STEPS + t) * HID + n] = h;
            if (t == T_STEPS - 1) hfin[b * HID + n] = h;
        }
        __syncthreads();   // h stores complete before release
        if (tid == 0) st_release_gpu(&g_flag[layer][bi * 32], (unsigned)(t + 1));
    }
}

// ------------------------- launch -------------------------
extern "C" void kernel_launch(void* const* d_in, const int* in_sizes, int n_in,
                              void* d_out, int out_size) {
    const float* x     = (const float*)d_in[0];
    const float* h0    = (const float*)d_in[1];
    const float* c0    = (const float*)d_in[2];
    const float* w_ih0 = (const float*)d_in[3];
    const float* w_hh0 = (const float*)d_in[4];
    const float* b_ih0 = (const float*)d_in[5];
    const float* b_hh0 = (const float*)d_in[6];
    const float* w_ih1 = (const float*)d_in[7];
    const float* w_hh1 = (const float*)d_in[8];
    const float* b_ih1 = (const float*)d_in[9];
    const float* b_hh1 = (const float*)d_in[10];
    float* out = (float*)d_out;

    const int rec_smem = (8192 + 5120 + 512 + 32) * 4;  // 55,424 B
    cudaFuncSetAttribute(lstm_rec, cudaFuncAttributeMaxDynamicSharedMemorySize, rec_smem);

    dim3 ggrid(16, 128);  // N-tiles x M-tiles

    // layer 0
    gemm_gates<<<ggrid, 256>>>(x, 0, w_ih0, b_ih0);
    lstm_rec<<<NBLK_R, 256, rec_smem>>>(w_hh0, b_hh0, h0, c0, out, 1, 0);

    // layer 1
    gemm_gates<<<ggrid, 256>>>(nullptr, 1, w_ih1, b_ih1);
    lstm_rec<<<NBLK_R, 256, rec_smem>>>(w_hh1, b_hh1, h0 + BATCH * HID, c0 + BATCH * HID,
                                        out + BATCH * HID, 0, 1);
}

// round 10
// speedup vs baseline: 1.2767x; 1.2767x over previous
#include <cuda_runtime.h>
#include <cstdint>
#include <math.h>

// Problem constants
#define T_STEPS 1024
#define BATCH   16
#define HID     512
#define NBLK    128    // 64 layer-0 blocks + 64 layer-1 blocks, one persistent kernel
#define RED_P   20     // padded row stride (floats): 80 B, 16B-aligned for float4

typedef unsigned long long ull;

// ------------------------- static device scratch -------------------------
__device__ float g_gx[(size_t)BATCH * T_STEPS * 4 * HID];   // layer-0 gate preactivations (input part)
__device__ float g_h0T[2][HID / 2][32];                     // h0 double-buffered, transposed pairs
__device__ float g_h1T[2][HID / 2][32];                     // h1 double-buffered
__device__ unsigned g_flag[NBLK * 32];                      // one flag per block, 128B stride

// ------------------------- helpers -------------------------
__device__ __forceinline__ ull ffma2(ull a, ull b, ull c) {
    ull d;
    asm("fma.rn.f32x2 %0, %1, %2, %3;" : "=l"(d) : "l"(a), "l"(b), "l"(c));
    return d;
}
__device__ __forceinline__ ull splat2(float a) {
    ull d;
    asm("mov.b64 %0, {%1, %1};" : "=l"(d) : "f"(a));
    return d;
}
__device__ __forceinline__ float2 unpack2(ull v) {
    float2 f;
    asm("mov.b64 {%0, %1}, %2;" : "=f"(f.x), "=f"(f.y) : "l"(v));
    return f;
}
__device__ __forceinline__ float sigm(float x) { return 1.0f / (1.0f + __expf(-x)); }
__device__ __forceinline__ void st_release_gpu(unsigned* p, unsigned v) {
    asm volatile("st.release.gpu.global.u32 [%0], %1;" :: "l"(p), "r"(v) : "memory");
}
__device__ __forceinline__ unsigned ld_acquire_gpu(const unsigned* p) {
    unsigned v;
    asm volatile("ld.acquire.gpu.global.u32 %0, [%1];" : "=r"(v) : "l"(p) : "memory");
    return v;
}

// ------------------------- flag reset (runs before the fused kernel) -------------------------
__global__ void init_flags() {
    g_flag[threadIdx.x * 32] = 0u;
}

// ------------------------- big GEMM: g_gx = x @ W_ih0^T + b_ih0 -------------------------
__global__ __launch_bounds__(256) void gemm_gates(const float* __restrict__ A,
                                                  const float* __restrict__ W,
                                                  const float* __restrict__ bias) {
    __shared__ float As[16][128];
    __shared__ float Bs[16][128];
    const int tid = threadIdx.x;
    const int tx = tid & 15, ty = tid >> 4;
    const int bn = blockIdx.x, bm = blockIdx.y;
    const float* Ab = A + (size_t)bm * 128 * 512;
    const float* Wb = W + (size_t)bn * 128 * 512;
    const int lr = tid >> 2;
    const int lc = (tid & 3) << 2;

    ull acc2[4][8];
#pragma unroll
    for (int i = 0; i < 4; i++)
#pragma unroll
        for (int j = 0; j < 8; j++) acc2[i][j] = 0ull;

    for (int k0 = 0; k0 < 512; k0 += 16) {
        float4 a0 = *(const float4*)(Ab + (size_t)lr * 512 + k0 + lc);
        float4 a1 = *(const float4*)(Ab + (size_t)(lr + 64) * 512 + k0 + lc);
        float4 w0 = *(const float4*)(Wb + (size_t)lr * 512 + k0 + lc);
        float4 w1 = *(const float4*)(Wb + (size_t)(lr + 64) * 512 + k0 + lc);
        __syncthreads();
        As[lc + 0][lr] = a0.x; As[lc + 1][lr] = a0.y; As[lc + 2][lr] = a0.z; As[lc + 3][lr] = a0.w;
        As[lc + 0][lr + 64] = a1.x; As[lc + 1][lr + 64] = a1.y; As[lc + 2][lr + 64] = a1.z; As[lc + 3][lr + 64] = a1.w;
        Bs[lc + 0][lr] = w0.x; Bs[lc + 1][lr] = w0.y; Bs[lc + 2][lr] = w0.z; Bs[lc + 3][lr] = w0.w;
        Bs[lc + 0][lr + 64] = w1.x; Bs[lc + 1][lr + 64] = w1.y; Bs[lc + 2][lr + 64] = w1.z; Bs[lc + 3][lr + 64] = w1.w;
        __syncthreads();
#pragma unroll
        for (int k = 0; k < 16; k++) {
            ulonglong2 av0 = *(const ulonglong2*)&As[k][ty * 8];
            ulonglong2 av1 = *(const ulonglong2*)&As[k][ty * 8 + 4];
            float4 bv0 = *(const float4*)&Bs[k][tx * 8];
            float4 bv1 = *(const float4*)&Bs[k][tx * 8 + 4];
            ull ap[4] = {av0.x, av0.y, av1.x, av1.y};
            ull bp[8] = {splat2(bv0.x), splat2(bv0.y), splat2(bv0.z), splat2(bv0.w),
                         splat2(bv1.x), splat2(bv1.y), splat2(bv1.z), splat2(bv1.w)};
#pragma unroll
            for (int i = 0; i < 4; i++)
#pragma unroll
                for (int j = 0; j < 8; j++) acc2[i][j] = ffma2(ap[i], bp[j], acc2[i][j]);
        }
    }

    const int ncol = bn * 128 + tx * 8;
    float bb[8];
#pragma unroll
    for (int j = 0; j < 8; j++) bb[j] = bias[ncol + j];
    float* Cb = g_gx + (size_t)(bm * 128 + ty * 8) * 2048 + ncol;
#pragma unroll
    for (int i2 = 0; i2 < 4; i2++) {
        float r0[8], r1[8];
#pragma unroll
        for (int j = 0; j < 8; j++) {
            float2 v = unpack2(acc2[i2][j]);
            r0[j] = v.x + bb[j];
            r1[j] = v.y + bb[j];
        }
        float* p0 = Cb + (size_t)(2 * i2) * 2048;
        float* p1 = p0 + 2048;
        *(float4*)(p0)     = make_float4(r0[0], r0[1], r0[2], r0[3]);
        *(float4*)(p0 + 4) = make_float4(r0[4], r0[5], r0[6], r0[7]);
        *(float4*)(p1)     = make_float4(r1[0], r1[1], r1[2], r1[3]);
        *(float4*)(p1 + 4) = make_float4(r1[4], r1[5], r1[6], r1[7]);
    }
}

// ------------------------- fused 2-layer pipelined recurrence -------------------------
// Blocks 0..63: layer 0 (step t = s). Blocks 64..127: layer 1 (step t = s-1),
// with input projection W_ih1 @ h0(t) fused as a concat-K GEMV (K = 1024).
// Single 128-flag barrier per global step; 1025 global steps total.
__global__ __launch_bounds__(256, 1) void lstm_fused(
    const float* __restrict__ w_hh0, const float* __restrict__ b_hh0,
    const float* __restrict__ w_ih1, const float* __restrict__ w_hh1,
    const float* __restrict__ b_ih1, const float* __restrict__ b_hh1,
    const float* __restrict__ h0in, const float* __restrict__ c0in,
    float* __restrict__ out) {
    extern __shared__ float smemf[];
    float* hs   = smemf;                       // L0: 8192 floats; L1: 16384 ([h1 | h0])
    float* red  = smemf + 16384;               // 8*32*RED_P = 5120
    float* gbuf = smemf + 16384 + 5120;        // 512
    float* bsm  = smemf + 16384 + 5120 + 512;  // 32

    const int tid = threadIdx.x;
    const int lane = tid & 31;
    const int wrp = tid >> 5;
    const bool isL1 = blockIdx.x >= 64;
    const int bi = blockIdx.x & 63;
    const int n0 = bi * 8;
    const int r = lane;                         // gate row 0..31
    const int grow = (r >> 3) * HID + n0 + (r & 7);

    // weight preload into registers
    ull wreg[64];
    if (!isL1) {
        const float4* wrow = (const float4*)(w_hh0 + (size_t)grow * HID + wrp * 64);
#pragma unroll
        for (int i = 0; i < 16; i++) {
            float4 v = __ldg(wrow + i);
            ulonglong2 uu = *(ulonglong2*)&v;
            wreg[2 * i] = uu.x;
            wreg[2 * i + 1] = uu.y;
        }
    } else {
        // concat K: warp wrp covers k in [wrp*128, wrp*128+128); k<512 -> w_hh1 (h1), else w_ih1 (h0)
#pragma unroll
        for (int i = 0; i < 32; i++) {
            int k = wrp * 128 + i * 4;
            const float4* src = (k < 512)
                ? (const float4*)(w_hh1 + (size_t)grow * HID + k)
                : (const float4*)(w_ih1 + (size_t)grow * HID + (k - 512));
            float4 v = __ldg(src);
            ulonglong2 uu = *(ulonglong2*)&v;
            wreg[2 * i] = uu.x;
            wreg[2 * i + 1] = uu.y;
        }
    }
    if (tid < 32) {
        int gr2 = (tid >> 3) * HID + n0 + (tid & 7);
        bsm[tid] = isL1 ? (__ldg(&b_ih1[gr2]) + __ldg(&b_hh1[gr2])) : __ldg(&b_hh0[gr2]);
    }

    const float* hinit = h0in + (isL1 ? BATCH * HID : 0);
    const float* c0l   = c0in + (isL1 ? BATCH * HID : 0);
    float c = 0.f;
    if (tid < 128) { int u = tid >> 4, b = tid & 15; c = __ldg(&c0l[b * HID + n0 + u]); }

    const int r_a = tid >> 4;       // 0..15
    const int b0 = tid & 15;
    const int r_b = r_a + 16;       // 16..31
    const int grow_a = (r_a >> 3) * HID + n0 + (r_a & 7);
    const int grow_b = (r_b >> 3) * HID + n0 + (r_b & 7);

    __syncthreads();

    for (int s = 0; s <= T_STEPS; s++) {
        const bool active = isL1 ? (s >= 1) : (s < T_STEPS);
        const int t = isL1 ? (s - 1) : s;

        // prefetch gx for layer-0 step (hides DRAM latency under the wait)
        float gx0 = 0.f, gx1 = 0.f;
        if (!isL1 && active) {
            gx0 = __ldg(&g_gx[((size_t)b0 * T_STEPS + t) * 2048 + grow_a]);
            gx1 = __ldg(&g_gx[((size_t)b0 * T_STEPS + t) * 2048 + grow_b]);
        }

        if (s > 0) {
            if (wrp == 0) {
                const unsigned tgt = (unsigned)s;
                const unsigned* f0 = &g_flag[(lane +  0) * 32];
                const unsigned* f1 = &g_flag[(lane + 32) * 32];
                const unsigned* f2 = &g_flag[(lane + 64) * 32];
                const unsigned* f3 = &g_flag[(lane + 96) * 32];
                bool ok;
                do {
                    ok = (ld_acquire_gpu(f0) >= tgt) & (ld_acquire_gpu(f1) >= tgt) &
                         (ld_acquire_gpu(f2) >= tgt) & (ld_acquire_gpu(f3) >= tgt);
                } while (!__all_sync(0xffffffffu, ok));
            }
            __syncthreads();
        }

        if (active) {
            // ---- stage h into shared ----
            if (!isL1) {
                if (t == 0) {
                    for (int i = tid; i < 8192; i += 256) {
                        int k2 = i >> 5, j = i & 31;
                        hs[i] = hinit[(j >> 1) * HID + 2 * k2 + (j & 1)];
                    }
                } else {
                    const float4* src = (const float4*)&g_h0T[(s - 1) & 1][0][0];
                    float4* dst = (float4*)hs;
#pragma unroll
                    for (int it = 0; it < 8; it++) {
                        int idx = tid + it * 256;
                        dst[idx] = __ldcg(src + idx);
                    }
                }
            } else {
                // h1(t-1) -> rows 0..255
                if (t == 0) {
                    for (int i = tid; i < 8192; i += 256) {
                        int k2 = i >> 5, j = i & 31;
                        hs[i] = hinit[(j >> 1) * HID + 2 * k2 + (j & 1)];
                    }
                } else {
                    const float4* src = (const float4*)&g_h1T[s & 1][0][0];
                    float4* dst = (float4*)hs;
#pragma unroll
                    for (int it = 0; it < 8; it++) {
                        int idx = tid + it * 256;
                        dst[idx] = __ldcg(src + idx);
                    }
                }
                // h0(t) -> rows 256..511
                {
                    const float4* src = (const float4*)&g_h0T[(s - 1) & 1][0][0];
                    float4* dst = (float4*)(hs + 8192);
#pragma unroll
                    for (int it = 0; it < 8; it++) {
                        int idx = tid + it * 256;
                        dst[idx] = __ldcg(src + idx);
                    }
                }
            }
            __syncthreads();

            // ---- GEMV (warp = K-slice, lane = gate row, h LDS are warp broadcasts) ----
            ull acc[16];
#pragma unroll
            for (int b = 0; b < 16; b++) acc[b] = 0ull;

            if (!isL1) {
                const ulonglong2* hbase = (const ulonglong2*)(hs + (wrp * 32) * 32);
#pragma unroll
                for (int kk = 0; kk < 32; kk++) {
                    const ulonglong2* hp = hbase + kk * 8;
#pragma unroll
                    for (int q = 0; q < 8; q++) {
                        ulonglong2 hv = hp[q];
                        acc[2 * q]     = ffma2(wreg[kk], hv.x, acc[2 * q]);
                        acc[2 * q + 1] = ffma2(wreg[kk], hv.y, acc[2 * q + 1]);
                    }
                }
            } else {
                const ulonglong2* hbase = (const ulonglong2*)(hs + (wrp * 64) * 32);
#pragma unroll
                for (int kk = 0; kk < 64; kk++) {
                    const ulonglong2* hp = hbase + kk * 8;
#pragma unroll
                    for (int q = 0; q < 8; q++) {
                        ulonglong2 hv = hp[q];
                        acc[2 * q]     = ffma2(wreg[kk], hv.x, acc[2 * q]);
                        acc[2 * q + 1] = ffma2(wreg[kk], hv.y, acc[2 * q + 1]);
                    }
                }
            }

            float p[16];
#pragma unroll
            for (int b = 0; b < 16; b++) {
                float2 v = unpack2(acc[b]);
                p[b] = v.x + v.y;
            }
            {
                float* rp = &red[(wrp * 32 + r) * RED_P];
#pragma unroll
                for (int q = 0; q < 4; q++)
                    *(float4*)&rp[q * 4] = make_float4(p[4 * q], p[4 * q + 1], p[4 * q + 2], p[4 * q + 3]);
            }
            __syncthreads();

            // ---- combine + activations (2 rows/thread) ----
            {
                float s0 = gx0 + bsm[r_a];
                float s1 = gx1 + bsm[r_b];
#pragma unroll
                for (int si = 0; si < 8; si++) {
                    s0 += red[(si * 32 + r_a) * RED_P + b0];
                    s1 += red[(si * 32 + r_b) * RED_P + b0];
                }
                float a0 = sigm(s0);                           // rows 0..15: i, f
                float a1 = (r_b < 24) ? tanhf(s1) : sigm(s1);  // 16..23: g, 24..31: o
                gbuf[r_a * 16 + b0] = a0;
                gbuf[r_b * 16 + b0] = a1;
            }
            __syncthreads();

            // ---- cell update + h publish ----
            if (tid < 128) {
                int u = tid >> 4, b = tid & 15;
                float iv = gbuf[(0 + u) * 16 + b];
                float fv = gbuf[(8 + u) * 16 + b];
                float gv = gbuf[(16 + u) * 16 + b];
                float ov = gbuf[(24 + u) * 16 + b];
                c = fv * c + iv * gv;
                float h = ov * tanhf(c);
                int n = n0 + u;
                if (!isL1) g_h0T[s & 1][n >> 1][b * 2 + (n & 1)] = h;
                else       g_h1T[(s - 1) & 1][n >> 1][b * 2 + (n & 1)] = h;
                if (t == T_STEPS - 1) out[(isL1 ? BATCH * HID : 0) + b * HID + n] = h;
            }
        }

        __threadfence();
        __syncthreads();
        if (tid == 0 && s < T_STEPS)
            st_release_gpu(&g_flag[blockIdx.x * 32], (unsigned)(s + 1));
    }
}

// ------------------------- launch -------------------------
extern "C" void kernel_launch(void* const* d_in, const int* in_sizes, int n_in,
                              void* d_out, int out_size) {
    const float* x     = (const float*)d_in[0];
    const float* h0    = (const float*)d_in[1];
    const float* c0    = (const float*)d_in[2];
    const float* w_ih0 = (const float*)d_in[3];
    const float* w_hh0 = (const float*)d_in[4];
    const float* b_ih0 = (const float*)d_in[5];
    const float* b_hh0 = (const float*)d_in[6];
    const float* w_ih1 = (const float*)d_in[7];
    const float* w_hh1 = (const float*)d_in[8];
    const float* b_ih1 = (const float*)d_in[9];
    const float* b_hh1 = (const float*)d_in[10];
    float* out = (float*)d_out;

    const int fused_smem = (16384 + 5120 + 512 + 32) * 4;  // 88,192 B
    cudaFuncSetAttribute(lstm_fused, cudaFuncAttributeMaxDynamicSharedMemorySize, fused_smem);

    init_flags<<<1, NBLK>>>();
    gemm_gates<<<dim3(16, 128), 256>>>(x, w_ih0, b_ih0);
    lstm_fused<<<NBLK, 256, fused_smem>>>(w_hh0, b_hh0, w_ih1, w_hh1, b_ih1, b_hh1,
                                          h0, c0, out);
}

// round 11
// speedup vs baseline: 1.4265x; 1.1173x over previous
#include <cuda_runtime.h>
#include <cstdint>
#include <math.h>

// Problem constants
#define T_STEPS 1024
#define BATCH   16
#define HID     512
#define NBLK    128    // 64 layer-0 blocks + 64 layer-1 blocks, one persistent kernel
#define RED_P   20     // padded row stride (floats): 80 B, 16B-aligned for float4

typedef unsigned long long ull;

// ------------------------- static device scratch -------------------------
__device__ float g_gx[(size_t)BATCH * T_STEPS * 4 * HID];   // layer-0 gate preactivations (input part)
__device__ float g_h0T[3][HID / 2][32];                     // h0 TRIPLE-buffered, transposed pairs
__device__ float g_h1T[2][HID / 2][32];                     // h1 double-buffered
__device__ unsigned g_flag[NBLK * 32];                      // one flag per block, 128B stride

// ------------------------- helpers -------------------------
__device__ __forceinline__ ull ffma2(ull a, ull b, ull c) {
    ull d;
    asm("fma.rn.f32x2 %0, %1, %2, %3;" : "=l"(d) : "l"(a), "l"(b), "l"(c));
    return d;
}
__device__ __forceinline__ ull splat2(float a) {
    ull d;
    asm("mov.b64 %0, {%1, %1};" : "=l"(d) : "f"(a));
    return d;
}
__device__ __forceinline__ float2 unpack2(ull v) {
    float2 f;
    asm("mov.b64 {%0, %1}, %2;" : "=f"(f.x), "=f"(f.y) : "l"(v));
    return f;
}
__device__ __forceinline__ float sigm(float x) { return 1.0f / (1.0f + __expf(-x)); }
__device__ __forceinline__ void st_release_gpu(unsigned* p, unsigned v) {
    asm volatile("st.release.gpu.global.u32 [%0], %1;" :: "l"(p), "r"(v) : "memory");
}
__device__ __forceinline__ unsigned ld_acquire_gpu(const unsigned* p) {
    unsigned v;
    asm volatile("ld.acquire.gpu.global.u32 %0, [%1];" : "=r"(v) : "l"(p) : "memory");
    return v;
}

// ------------------------- flag reset (runs before the fused kernel) -------------------------
__global__ void init_flags() {
    g_flag[threadIdx.x * 32] = 0u;
}

// ------------------------- big GEMM: g_gx = x @ W_ih0^T + b_ih0 -------------------------
__global__ __launch_bounds__(256) void gemm_gates(const float* __restrict__ A,
                                                  const float* __restrict__ W,
                                                  const float* __restrict__ bias) {
    __shared__ float As[16][128];
    __shared__ float Bs[16][128];
    const int tid = threadIdx.x;
    const int tx = tid & 15, ty = tid >> 4;
    const int bn = blockIdx.x, bm = blockIdx.y;
    const float* Ab = A + (size_t)bm * 128 * 512;
    const float* Wb = W + (size_t)bn * 128 * 512;
    const int lr = tid >> 2;
    const int lc = (tid & 3) << 2;

    ull acc2[4][8];
#pragma unroll
    for (int i = 0; i < 4; i++)
#pragma unroll
        for (int j = 0; j < 8; j++) acc2[i][j] = 0ull;

    for (int k0 = 0; k0 < 512; k0 += 16) {
        float4 a0 = *(const float4*)(Ab + (size_t)lr * 512 + k0 + lc);
        float4 a1 = *(const float4*)(Ab + (size_t)(lr + 64) * 512 + k0 + lc);
        float4 w0 = *(const float4*)(Wb + (size_t)lr * 512 + k0 + lc);
        float4 w1 = *(const float4*)(Wb + (size_t)(lr + 64) * 512 + k0 + lc);
        __syncthreads();
        As[lc + 0][lr] = a0.x; As[lc + 1][lr] = a0.y; As[lc + 2][lr] = a0.z; As[lc + 3][lr] = a0.w;
        As[lc + 0][lr + 64] = a1.x; As[lc + 1][lr + 64] = a1.y; As[lc + 2][lr + 64] = a1.z; As[lc + 3][lr + 64] = a1.w;
        Bs[lc + 0][lr] = w0.x; Bs[lc + 1][lr] = w0.y; Bs[lc + 2][lr] = w0.z; Bs[lc + 3][lr] = w0.w;
        Bs[lc + 0][lr + 64] = w1.x; Bs[lc + 1][lr + 64] = w1.y; Bs[lc + 2][lr + 64] = w1.z; Bs[lc + 3][lr + 64] = w1.w;
        __syncthreads();
#pragma unroll
        for (int k = 0; k < 16; k++) {
            ulonglong2 av0 = *(const ulonglong2*)&As[k][ty * 8];
            ulonglong2 av1 = *(const ulonglong2*)&As[k][ty * 8 + 4];
            float4 bv0 = *(const float4*)&Bs[k][tx * 8];
            float4 bv1 = *(const float4*)&Bs[k][tx * 8 + 4];
            ull ap[4] = {av0.x, av0.y, av1.x, av1.y};
            ull bp[8] = {splat2(bv0.x), splat2(bv0.y), splat2(bv0.z), splat2(bv0.w),
                         splat2(bv1.x), splat2(bv1.y), splat2(bv1.z), splat2(bv1.w)};
#pragma unroll
            for (int i = 0; i < 4; i++)
#pragma unroll
                for (int j = 0; j < 8; j++) acc2[i][j] = ffma2(ap[i], bp[j], acc2[i][j]);
        }
    }

    const int ncol = bn * 128 + tx * 8;
    float bb[8];
#pragma unroll
    for (int j = 0; j < 8; j++) bb[j] = bias[ncol + j];
    float* Cb = g_gx + (size_t)(bm * 128 + ty * 8) * 2048 + ncol;
#pragma unroll
    for (int i2 = 0; i2 < 4; i2++) {
        float r0[8], r1[8];
#pragma unroll
        for (int j = 0; j < 8; j++) {
            float2 v = unpack2(acc2[i2][j]);
            r0[j] = v.x + bb[j];
            r1[j] = v.y + bb[j];
        }
        float* p0 = Cb + (size_t)(2 * i2) * 2048;
        float* p1 = p0 + 2048;
        *(float4*)(p0)     = make_float4(r0[0], r0[1], r0[2], r0[3]);
        *(float4*)(p0 + 4) = make_float4(r0[4], r0[5], r0[6], r0[7]);
        *(float4*)(p1)     = make_float4(r1[0], r1[1], r1[2], r1[3]);
        *(float4*)(p1 + 4) = make_float4(r1[4], r1[5], r1[6], r1[7]);
    }
}

// ------------------------- fused 2-layer pipelined recurrence -------------------------
// Blocks 0..63: layer 0 (step t = s). Blocks 64..127: layer 1 (step t = s-1).
// Decoupled waits: L0 waits (flagL0 >= s, flagL1 >= s-1)  [triple-buffered h0];
// L1 warps 0-3 (h1 K-half) wait flagL1 >= s; warps 4-7 (h0 K-half) wait flagL0 >= s.
// Staging is warp-local (each warp stages exactly the K-slice its GEMV reads).
__global__ __launch_bounds__(256, 1) void lstm_fused(
    const float* __restrict__ w_hh0, const float* __restrict__ b_hh0,
    const float* __restrict__ w_ih1, const float* __restrict__ w_hh1,
    const float* __restrict__ b_ih1, const float* __restrict__ b_hh1,
    const float* __restrict__ h0in, const float* __restrict__ c0in,
    float* __restrict__ out) {
    extern __shared__ float smemf[];
    float* hs   = smemf;                       // L0: 8192 floats; L1: 16384 ([h1 | h0])
    float* red  = smemf + 16384;               // 8*32*RED_P = 5120
    float* gbuf = smemf + 16384 + 5120;        // 512
    float* bsm  = smemf + 16384 + 5120 + 512;  // 32

    const int tid = threadIdx.x;
    const int lane = tid & 31;
    const int wrp = tid >> 5;
    const bool isL1 = blockIdx.x >= 64;
    const int bi = blockIdx.x & 63;
    const int n0 = bi * 8;
    const int r = lane;                         // gate row 0..31
    const int grow = (r >> 3) * HID + n0 + (r & 7);

    // weight preload into registers
    ull wreg[64];
    if (!isL1) {
        const float4* wrow = (const float4*)(w_hh0 + (size_t)grow * HID + wrp * 64);
#pragma unroll
        for (int i = 0; i < 16; i++) {
            float4 v = __ldg(wrow + i);
            ulonglong2 uu = *(ulonglong2*)&v;
            wreg[2 * i] = uu.x;
            wreg[2 * i + 1] = uu.y;
        }
    } else {
        // concat K: warps 0-3 cover k in [0,512) -> w_hh1 (h1); warps 4-7 cover [512,1024) -> w_ih1 (h0)
#pragma unroll
        for (int i = 0; i < 32; i++) {
            int k = wrp * 128 + i * 4;
            const float4* src = (k < 512)
                ? (const float4*)(w_hh1 + (size_t)grow * HID + k)
                : (const float4*)(w_ih1 + (size_t)grow * HID + (k - 512));
            float4 v = __ldg(src);
            ulonglong2 uu = *(ulonglong2*)&v;
            wreg[2 * i] = uu.x;
            wreg[2 * i + 1] = uu.y;
        }
    }
    if (tid < 32) {
        int gr2 = (tid >> 3) * HID + n0 + (tid & 7);
        bsm[tid] = isL1 ? (__ldg(&b_ih1[gr2]) + __ldg(&b_hh1[gr2])) : __ldg(&b_hh0[gr2]);
    }

    const float* hinit = h0in + (isL1 ? BATCH * HID : 0);
    const float* c0l   = c0in + (isL1 ? BATCH * HID : 0);
    float c = 0.f;
    if (tid < 128) { int u = tid >> 4, b = tid & 15; c = __ldg(&c0l[b * HID + n0 + u]); }

    const int r_a = tid >> 4;       // 0..15
    const int b0 = tid & 15;
    const int r_b = r_a + 16;       // 16..31
    const int grow_a = (r_a >> 3) * HID + n0 + (r_a & 7);
    const int grow_b = (r_b >> 3) * HID + n0 + (r_b & 7);

    __syncthreads();

    for (int s = 0; s <= T_STEPS; s++) {
        const bool active = isL1 ? (s >= 1) : (s < T_STEPS);
        const int t = isL1 ? (s - 1) : s;

        if (active) {
            if (!isL1) {
                // ---- layer 0: wait + warp-local stage ----
                float gx0 = __ldg(&g_gx[((size_t)b0 * T_STEPS + t) * 2048 + grow_a]);
                float gx1 = __ldg(&g_gx[((size_t)b0 * T_STEPS + t) * 2048 + grow_b]);

                if (s == 0) {
                    for (int i = tid; i < 8192; i += 256) {
                        int k2 = i >> 5, j = i & 31;
                        hs[i] = hinit[(j >> 1) * HID + 2 * k2 + (j & 1)];
                    }
                    __syncthreads();
                } else {
                    // every warp: flagL0 >= s  AND  flagL1 >= s-1 (h0 buffer free)
                    const unsigned tgt = (unsigned)s;
                    {
                        const unsigned* f0 = &g_flag[lane * 32];
                        const unsigned* f1 = &g_flag[(lane + 32) * 32];
                        const unsigned* f2 = &g_flag[(64 + lane) * 32];
                        const unsigned* f3 = &g_flag[(96 + lane) * 32];
                        bool ok;
                        do {
                            ok = (ld_acquire_gpu(f0) >= tgt) & (ld_acquire_gpu(f1) >= tgt) &
                                 (ld_acquire_gpu(f2) + 1u >= tgt) & (ld_acquire_gpu(f3) + 1u >= tgt);
                        } while (!__all_sync(0xffffffffu, ok));
                    }
                    // warp-local stage: warp wrp covers 256 float4 of its own K-slice
                    const float4* src = (const float4*)&g_h0T[(s - 1) % 3][0][0];
                    float4* dst = (float4*)hs;
                    const int base = wrp * 256;
#pragma unroll
                    for (int it = 0; it < 8; it++) {
                        int idx = base + lane + it * 32;
                        dst[idx] = __ldcg(src + idx);
                    }
                }

                // ---- GEMV (warp-local K-slice) ----
                ull acc[16];
#pragma unroll
                for (int b = 0; b < 16; b++) acc[b] = 0ull;
                const ulonglong2* hbase = (const ulonglong2*)(hs + (wrp * 32) * 32);
#pragma unroll
                for (int kk = 0; kk < 32; kk++) {
                    const ulonglong2* hp = hbase + kk * 8;
#pragma unroll
                    for (int q = 0; q < 8; q++) {
                        ulonglong2 hv = hp[q];
                        acc[2 * q]     = ffma2(wreg[kk], hv.x, acc[2 * q]);
                        acc[2 * q + 1] = ffma2(wreg[kk], hv.y, acc[2 * q + 1]);
                    }
                }
                float p[16];
#pragma unroll
                for (int b = 0; b < 16; b++) {
                    float2 v = unpack2(acc[b]);
                    p[b] = v.x + v.y;
                }
                {
                    float* rp = &red[(wrp * 32 + r) * RED_P];
#pragma unroll
                    for (int q = 0; q < 4; q++)
                        *(float4*)&rp[q * 4] = make_float4(p[4 * q], p[4 * q + 1], p[4 * q + 2], p[4 * q + 3]);
                }
                __syncthreads();

                // ---- combine + activations ----
                {
                    float s0 = gx0 + bsm[r_a];
                    float s1 = gx1 + bsm[r_b];
#pragma unroll
                    for (int si = 0; si < 8; si++) {
                        s0 += red[(si * 32 + r_a) * RED_P + b0];
                        s1 += red[(si * 32 + r_b) * RED_P + b0];
                    }
                    float a0 = sigm(s0);
                    float a1 = (r_b < 24) ? tanhf(s1) : sigm(s1);
                    gbuf[r_a * 16 + b0] = a0;
                    gbuf[r_b * 16 + b0] = a1;
                }
                __syncthreads();

                if (tid < 128) {
                    int u = tid >> 4, b = tid & 15;
                    float iv = gbuf[(0 + u) * 16 + b];
                    float fv = gbuf[(8 + u) * 16 + b];
                    float gv = gbuf[(16 + u) * 16 + b];
                    float ov = gbuf[(24 + u) * 16 + b];
                    c = fv * c + iv * gv;
                    float h = ov * tanhf(c);
                    int n = n0 + u;
                    g_h0T[s % 3][n >> 1][b * 2 + (n & 1)] = h;
                    if (t == T_STEPS - 1) out[b * HID + n] = h;
                }
            } else {
                // ---- layer 1 ----
                // h1 half (warps 0-3): wait flagL1 >= s, stage h1(t-1)
                if (s == 1) {
                    for (int i = tid; i < 8192; i += 256) {
                        int k2 = i >> 5, j = i & 31;
                        hs[i] = hinit[(j >> 1) * HID + 2 * k2 + (j & 1)];
                    }
                    __syncthreads();
                } else if (wrp < 4) {
                    const unsigned tgt = (unsigned)s;
                    const unsigned* f0 = &g_flag[(64 + lane) * 32];
                    const unsigned* f1 = &g_flag[(96 + lane) * 32];
                    bool ok;
                    do {
                        ok = (ld_acquire_gpu(f0) >= tgt) & (ld_acquire_gpu(f1) >= tgt);
                    } while (!__all_sync(0xffffffffu, ok));
                    const float4* src = (const float4*)&g_h1T[s & 1][0][0];
                    float4* dst = (float4*)hs;
                    const int base = wrp * 512;
#pragma unroll
                    for (int it = 0; it < 16; it++) {
                        int idx = base + lane + it * 32;
                        dst[idx] = __ldcg(src + idx);
                    }
                }
                // h0 half (warps 4-7): wait flagL0 >= s, stage h0(t)
                if (wrp >= 4) {
                    const unsigned tgt = (unsigned)s;
                    const unsigned* f0 = &g_flag[lane * 32];
                    const unsigned* f1 = &g_flag[(lane + 32) * 32];
                    bool ok;
                    do {
                        ok = (ld_acquire_gpu(f0) >= tgt) & (ld_acquire_gpu(f1) >= tgt);
                    } while (!__all_sync(0xffffffffu, ok));
                    const float4* src = (const float4*)&g_h0T[(s - 1) % 3][0][0];
                    float4* dst = (float4*)(hs + 8192);
                    const int base = (wrp - 4) * 512;
#pragma unroll
                    for (int it = 0; it < 16; it++) {
                        int idx = base + lane + it * 32;
                        dst[idx] = __ldcg(src + idx);
                    }
                }

                // ---- GEMV (warp-local 128-k slice of concat K) ----
                ull acc[16];
#pragma unroll
                for (int b = 0; b < 16; b++) acc[b] = 0ull;
                const ulonglong2* hbase = (const ulonglong2*)(hs + (wrp * 64) * 32);
#pragma unroll
                for (int kk = 0; kk < 64; kk++) {
                    const ulonglong2* hp = hbase + kk * 8;
#pragma unroll
                    for (int q = 0; q < 8; q++) {
                        ulonglong2 hv = hp[q];
                        acc[2 * q]     = ffma2(wreg[kk], hv.x, acc[2 * q]);
                        acc[2 * q + 1] = ffma2(wreg[kk], hv.y, acc[2 * q + 1]);
                    }
                }
                float p[16];
#pragma unroll
                for (int b = 0; b < 16; b++) {
                    float2 v = unpack2(acc[b]);
                    p[b] = v.x + v.y;
                }
                {
                    float* rp = &red[(wrp * 32 + r) * RED_P];
#pragma unroll
                    for (int q = 0; q < 4; q++)
                        *(float4*)&rp[q * 4] = make_float4(p[4 * q], p[4 * q + 1], p[4 * q + 2], p[4 * q + 3]);
                }
                __syncthreads();

                // ---- combine + activations ----
                {
                    float s0 = bsm[r_a];
                    float s1 = bsm[r_b];
#pragma unroll
                    for (int si = 0; si < 8; si++) {
                        s0 += red[(si * 32 + r_a) * RED_P + b0];
                        s1 += red[(si * 32 + r_b) * RED_P + b0];
                    }
                    float a0 = sigm(s0);
                    float a1 = (r_b < 24) ? tanhf(s1) : sigm(s1);
                    gbuf[r_a * 16 + b0] = a0;
                    gbuf[r_b * 16 + b0] = a1;
                }
                __syncthreads();

                if (tid < 128) {
                    int u = tid >> 4, b = tid & 15;
                    float iv = gbuf[(0 + u) * 16 + b];
                    float fv = gbuf[(8 + u) * 16 + b];
                    float gv = gbuf[(16 + u) * 16 + b];
                    float ov = gbuf[(24 + u) * 16 + b];
                    c = fv * c + iv * gv;
                    float h = ov * tanhf(c);
                    int n = n0 + u;
                    g_h1T[(s - 1) & 1][n >> 1][b * 2 + (n & 1)] = h;
                    if (t == T_STEPS - 1) out[BATCH * HID + b * HID + n] = h;
                }
            }
        }

        __threadfence();
        __syncthreads();
        if (tid == 0 && s < T_STEPS)
            st_release_gpu(&g_flag[blockIdx.x * 32], (unsigned)(s + 1));
    }
}

// ------------------------- launch -------------------------
extern "C" void kernel_launch(void* const* d_in, const int* in_sizes, int n_in,
                              void* d_out, int out_size) {
    const float* x     = (const float*)d_in[0];
    const float* h0    = (const float*)d_in[1];
    const float* c0    = (const float*)d_in[2];
    const float* w_ih0 = (const float*)d_in[3];
    const float* w_hh0 = (const float*)d_in[4];
    const float* b_ih0 = (const float*)d_in[5];
    const float* b_hh0 = (const float*)d_in[6];
    const float* w_ih1 = (const float*)d_in[7];
    const float* w_hh1 = (const float*)d_in[8];
    const float* b_ih1 = (const float*)d_in[9];
    const float* b_hh1 = (const float*)d_in[10];
    float* out = (float*)d_out;

    const int fused_smem = (16384 + 5120 + 512 + 32) * 4;  // 88,192 B
    cudaFuncSetAttribute(lstm_fused, cudaFuncAttributeMaxDynamicSharedMemorySize, fused_smem);

    init_flags<<<1, NBLK>>>();
    gemm_gates<<<dim3(16, 128), 256>>>(x, w_ih0, b_ih0);
    lstm_fused<<<NBLK, 256, fused_smem>>>(w_hh0, b_hh0, w_ih1, w_hh1, b_ih1, b_hh1,
                                          h0, c0, out);
}